// round 3
// baseline (speedup 1.0000x reference)
#include <cuda_runtime.h>

#define BB 32
#define TT_IN 1024
#define TP 1025
#define EMB 384
#define GC 96
#define NI4 24           // GC/4 input-channel quads
#define NWARPS 12
#define CTILE 32         // time steps per conv block
#define XROWS (CTILE + 2)

// Scratch (device globals: no allocations allowed)
__device__ int        g_cum[BB * TP];
__device__ ulonglong2 g_wt4[3 * NI4 * EMB];  // [k][i4][c]: 4 floats = w[c][4i4..4i4+3][k]

// Packed fp32x2 FMA (Blackwell): d.lo+=a.lo*b.lo ; d.hi+=a.hi*b.hi
#define FFMA2(acc, a, b) \
    asm("fma.rn.f32x2 %0, %1, %2, %0;" : "+l"(acc) : "l"(a), "l"(b))

// ---------------------------------------------------------------------------
// Pack conv1 weights [c][i][k] -> float4 quads [k][i4][c]
// ---------------------------------------------------------------------------
__global__ void transpose_w_kernel(const float* __restrict__ w1) {
    int idx = blockIdx.x * blockDim.x + threadIdx.x;
    if (idx >= 3 * NI4 * EMB) return;
    int c  = idx % EMB;
    int i4 = (idx / EMB) % NI4;
    int k  = idx / (EMB * NI4);
    float4 p;
    p.x = w1[c * (GC * 3) + (4 * i4 + 0) * 3 + k];
    p.y = w1[c * (GC * 3) + (4 * i4 + 1) * 3 + k];
    p.z = w1[c * (GC * 3) + (4 * i4 + 2) * 3 + k];
    p.w = w1[c * (GC * 3) + (4 * i4 + 3) * 3 + k];
    g_wt4[idx] = *(ulonglong2*)&p;
}

// ---------------------------------------------------------------------------
// Inclusive cumsum of durations per batch row (one block per b)
// ---------------------------------------------------------------------------
__global__ void cumsum_kernel(const int* __restrict__ dur) {
    const int b = blockIdx.x;
    const int tid = threadIdx.x;           // 256 threads
    const int CH = 5;                      // 256*5 = 1280 >= 1025
    __shared__ int part[256];

    int base = tid * CH;
    int s = 0;
#pragma unroll
    for (int j = 0; j < CH; j++) {
        int p = base + j;
        if (p < TP) s += dur[b * TP + p];
    }
    part[tid] = s;
    __syncthreads();

    for (int off = 1; off < 256; off <<= 1) {
        int v = (tid >= off) ? part[tid - off] : 0;
        __syncthreads();
        part[tid] += v;
        __syncthreads();
    }

    int run = (tid > 0) ? part[tid - 1] : 0;
#pragma unroll
    for (int j = 0; j < CH; j++) {
        int p = base + j;
        if (p < TP) {
            run += dur[b * TP + p];
            g_cum[b * TP + p] = run;
        }
    }
}

// ---------------------------------------------------------------------------
// Fused duration predictor, f32x2-packed, 4-channel quads, CTILE=32.
// Scatter-form inner loop: each x row position loaded exactly once (LDS.128
// broadcast), contributing to acc[lt], acc[lt-1], acc[lt-2] with w_k quads.
// Weight quads double-buffered across the i4 loop.
// ---------------------------------------------------------------------------
extern __shared__ float s_mem[];

__global__ __launch_bounds__(384, 1)
void conv_kernel(const float* __restrict__ ph,
                 const float* __restrict__ sil,
                 const float* __restrict__ b1,
                 const float* __restrict__ w2,
                 const float* __restrict__ b2,
                 float* __restrict__ dpred) {
    float* xs  = s_mem;                    // XROWS * EMB floats, [t][c]
    float* red = s_mem + XROWS * EMB;      // NWARPS * CTILE

    const int b   = blockIdx.y;
    const int t0  = blockIdx.x * CTILE;
    const int tid = threadIdx.x;           // output channel c

    // Stage x tile [t][c]: global t = t0-1+lt; t==1024 -> silence; else zero.
#pragma unroll
    for (int lt = 0; lt < XROWS; lt++) {
        int tg = t0 - 1 + lt;
        float v = 0.f;
        if ((unsigned)tg < TT_IN)  v = ph[((size_t)b * TT_IN + tg) * EMB + tid];
        else if (tg == TT_IN)      v = sil[tid];
        xs[lt * EMB + tid] = v;
    }
    __syncthreads();

    const int cbase = (tid / GC) * GC;     // group channel base

    unsigned long long acc[CTILE];
#pragma unroll
    for (int t = 0; t < CTILE; t++) acc[t] = 0ULL;

    // Weight double-buffer
    const ulonglong2* wq = g_wt4 + tid;
    ulonglong2 w0 = wq[(0 * NI4 + 0) * EMB];
    ulonglong2 w1 = wq[(1 * NI4 + 0) * EMB];
    ulonglong2 w2q = wq[(2 * NI4 + 0) * EMB];

    for (int i4 = 0; i4 < NI4; i4++) {
        int nx = (i4 + 1 < NI4) ? (i4 + 1) : i4;
        ulonglong2 n0 = wq[(0 * NI4 + nx) * EMB];
        ulonglong2 n1 = wq[(1 * NI4 + nx) * EMB];
        ulonglong2 n2 = wq[(2 * NI4 + nx) * EMB];

        const ulonglong2* xq =
            (const ulonglong2*)(xs + cbase + 4 * i4);   // stride EMB floats per row
#pragma unroll
        for (int lt = 0; lt < XROWS; lt++) {
            ulonglong2 x = xq[lt * (EMB / 4)];
            if (lt < CTILE)               { FFMA2(acc[lt],     w0.x,  x.x); FFMA2(acc[lt],     w0.y,  x.y); }
            if (lt >= 1 && lt - 1 < CTILE){ FFMA2(acc[lt - 1], w1.x,  x.x); FFMA2(acc[lt - 1], w1.y,  x.y); }
            if (lt >= 2)                  { FFMA2(acc[lt - 2], w2q.x, x.x); FFMA2(acc[lt - 2], w2q.y, x.y); }
        }
        w0 = n0; w1 = n1; w2q = n2;
    }

    // Epilogue: lo+hi+bias, ReLU, * w2[c], reduce over 384 channels.
    const float bias  = b1[tid];
    const float w2c   = w2[tid];
    const int lane = tid & 31;
    const int warp = tid >> 5;
#pragma unroll
    for (int t = 0; t < CTILE; t++) {
        unsigned lo, hi;
        asm("mov.b64 {%0,%1}, %2;" : "=r"(lo), "=r"(hi) : "l"(acc[t]));
        float v = __uint_as_float(lo) + __uint_as_float(hi) + bias;
        v = w2c * fmaxf(v, 0.f);
        v += __shfl_down_sync(0xffffffffu, v, 16);
        v += __shfl_down_sync(0xffffffffu, v, 8);
        v += __shfl_down_sync(0xffffffffu, v, 4);
        v += __shfl_down_sync(0xffffffffu, v, 2);
        v += __shfl_down_sync(0xffffffffu, v, 1);
        if (lane == 0) red[warp * CTILE + t] = v;
    }
    __syncthreads();

    if (tid < CTILE) {
        int t = t0 + tid;
        if (t < TP) {
            float s = b2[0];
#pragma unroll
            for (int w = 0; w < NWARPS; w++) s += red[w * CTILE + tid];
            dpred[b * TP + t] = s;
        }
    }
}

// ---------------------------------------------------------------------------
// Length regulation by SCATTER: one warp per (b, token j).
// Streaming stores keep the 183MB write-once output out of L2's way.
// ---------------------------------------------------------------------------
__global__ void scatter_kernel(const float* __restrict__ ph,
                               const float* __restrict__ sil,
                               float* __restrict__ out,
                               int t_out) {
    const int w = (blockIdx.x * blockDim.x + threadIdx.x) >> 5;
    const int lane = threadIdx.x & 31;
    if (w >= BB * TP) return;
    const int b = w / TP;
    const int j = w - b * TP;

    const int hi = g_cum[b * TP + j];
    const int lo = j ? g_cum[b * TP + j - 1] : 0;
    const int d = hi - lo;
    if (d <= 0) return;

    const float4* src = (j < TT_IN)
        ? (const float4*)(ph + ((size_t)b * TT_IN + j) * EMB)
        : (const float4*)sil;
    float4 r0 = __ldcs(src + lane);
    float4 r1 = __ldcs(src + 32 + lane);
    float4 r2 = __ldcs(src + 64 + lane);

    float4* dst = (float4*)(out + ((size_t)b * t_out + lo) * EMB);
    for (int f = 0; f < d; f++, dst += EMB / 4) {
        __stcs(dst + lane,      r0);
        __stcs(dst + 32 + lane, r1);
        __stcs(dst + 64 + lane, r2);
    }
}

// Zero-fill frames past each batch's total length (out buffer is poisoned).
__global__ void zerotail_kernel(float* __restrict__ out, int t_out) {
    const int b = blockIdx.x;
    const int tot = g_cum[b * TP + TP - 1];
    if (tot >= t_out) return;
    float4* dst = (float4*)(out + ((size_t)b * t_out + tot) * EMB);
    const int n4 = (t_out - tot) * (EMB / 4);
    const float4 z = make_float4(0.f, 0.f, 0.f, 0.f);
    for (int i = threadIdx.x; i < n4; i += blockDim.x) __stcs(dst + i, z);
}

// ---------------------------------------------------------------------------
// Launch
// ---------------------------------------------------------------------------
extern "C" void kernel_launch(void* const* d_in, const int* in_sizes, int n_in,
                              void* d_out, int out_size) {
    const float* ph  = (const float*)d_in[0];   // [32,1024,384]
    const float* sil = (const float*)d_in[1];   // [384]
    const float* w1  = (const float*)d_in[2];   // [384,96,3]
    const float* b1  = (const float*)d_in[3];   // [384]
    const float* w2  = (const float*)d_in[4];   // [1,384,1]
    const float* b2  = (const float*)d_in[5];   // [1]
    const int*   dur = (const int*)d_in[6];     // [32,1025]

    const int t_out = (out_size - BB * TP) / (BB * EMB);

    float* out_exp  = (float*)d_out;                             // [B,t_out,EMB]
    float* out_pred = (float*)d_out + (size_t)BB * t_out * EMB;  // [B,TP]

    transpose_w_kernel<<<(3 * NI4 * EMB + 255) / 256, 256>>>(w1);
    cumsum_kernel<<<BB, 256>>>(dur);

    const int smem_bytes = (XROWS * EMB + NWARPS * CTILE) * (int)sizeof(float);
    cudaFuncSetAttribute(conv_kernel,
                         cudaFuncAttributeMaxDynamicSharedMemorySize, smem_bytes);
    dim3 cgrid((TP + CTILE - 1) / CTILE, BB);
    conv_kernel<<<cgrid, EMB, smem_bytes>>>(ph, sil, b1, w2, b2, out_pred);

    const int warps = BB * TP;
    scatter_kernel<<<(warps * 32 + 255) / 256, 256>>>(ph, sil, out_exp, t_out);
    zerotail_kernel<<<BB, 256>>>(out_exp, t_out);
}